// round 12
// baseline (speedup 1.0000x reference)
#include <cuda_runtime.h>
#include <cuda_fp16.h>
#include <cstdint>

// Journal:
//  - tcgen05/TMEM unusable (compute_103 PTX target). HMMA (mma.sync) works.
//  - qkv: double-buffered 3-term split-fp16 HMMA (R10/R11, ~40us).
//  - attn: FFMA2 block-staged oproj epilogue (HMMA epilogue regressed, R10).
//  - R12: attn reg-diet (idx re-shuffle, launch_bounds(256,5)) + 2x4 epilogue.

#define NPTS 100000
#define CDIM 64
#define TILE 64
#define SK   72   // smem row stride in halves (conflict-free ldmatrix)

// Scratch (device globals — no allocations allowed in kernel_launch)
__device__ float  g_q[NPTS * CDIM];
__device__ __half g_k[NPTS * CDIM];
__device__ __half g_v[NPTS * CDIM];

typedef unsigned long long u64;

__device__ __forceinline__ uint32_t smem_to_u32(const void* p) {
    uint32_t a;
    asm("{ .reg .u64 t; cvta.to.shared.u64 t, %1; cvt.u32.u64 %0, t; }" : "=r"(a) : "l"(p));
    return a;
}
__device__ __forceinline__ void fma2(u64& d, u64 a, u64 b) {
    asm("fma.rn.f32x2 %0, %1, %2, %0;" : "+l"(d) : "l"(a), "l"(b));
}
__device__ __forceinline__ void unpack2(u64 v, float& lo, float& hi) {
    asm("mov.b64 {%0, %1}, %2;" : "=f"(lo), "=f"(hi) : "l"(v));
}
__device__ __forceinline__ u64 pack2f(float lo, float hi) {
    u64 r;
    asm("mov.b64 %0, {%1, %2};" : "=l"(r) : "f"(lo), "f"(hi));
    return r;
}

// ---- HMMA building blocks (sm_80-era PTX, valid on compute_103) ----
__device__ __forceinline__ void ldm_x4(uint32_t* r, uint32_t addr) {
    asm volatile("ldmatrix.sync.aligned.m8n8.x4.shared.b16 {%0,%1,%2,%3}, [%4];"
                 : "=r"(r[0]), "=r"(r[1]), "=r"(r[2]), "=r"(r[3]) : "r"(addr));
}
__device__ __forceinline__ void ldm_x2(uint32_t* r, uint32_t addr) {
    asm volatile("ldmatrix.sync.aligned.m8n8.x2.shared.b16 {%0,%1}, [%2];"
                 : "=r"(r[0]), "=r"(r[1]) : "r"(addr));
}
__device__ __forceinline__ void mma16816(float* c, const uint32_t* a, const uint32_t* b) {
    asm volatile("mma.sync.aligned.m16n8k16.row.col.f32.f16.f16.f32 "
                 "{%0,%1,%2,%3}, {%4,%5,%6,%7}, {%8,%9}, {%0,%1,%2,%3};"
                 : "+f"(c[0]), "+f"(c[1]), "+f"(c[2]), "+f"(c[3])
                 : "r"(a[0]), "r"(a[1]), "r"(a[2]), "r"(a[3]), "r"(b[0]), "r"(b[1]));
}

// fp32 -> (hi, lo) fp16 split: hi + lo ≈ x with ~2^-22 relative error.
__device__ __forceinline__ void split_f16(float x, __half& hi, __half& lo) {
    hi = __float2half_rn(x);
    lo = __float2half_rn(x - __half2float(hi));
}

// ---------------------------------------------------------------------------
// Kernel 1: q/k/v projection on the tensor pipe, double-buffered A (R10/R11).
// ---------------------------------------------------------------------------
extern __shared__ __align__(16) char qkv_sm[];

#define ABUF_BYTES (64 * SK * 2)          // one A matrix (hi or lo): 9216 B
#define ABUF_PAIR  (2 * ABUF_BYTES)       // hi+lo: 18432 B

__device__ __forceinline__ void qkv_load_regs(uint4* nf, const float* feats,
                                              int row0, int N, int tid)
{
#pragma unroll
    for (int i = 0; i < 4; i++) {
        int e = tid + (i << 8);
        int row = row0 + (e >> 4);
        nf[i] = make_uint4(0u, 0u, 0u, 0u);
        if (row < N)
            nf[i] = *(const uint4*)(feats + (size_t)row * 64 + ((e & 15) << 2));
    }
}

__device__ __forceinline__ void qkv_convert_store(char* abuf, const uint4* nf, int tid)
{
    __half* hi = (__half*)abuf;
    __half* lo = (__half*)(abuf + ABUF_BYTES);
#pragma unroll
    for (int i = 0; i < 4; i++) {
        int e = tid + (i << 8);
        int r = e >> 4, c4 = (e & 15) << 2;
        float4 v = *(const float4*)&nf[i];
        __half h0, l0, h1, l1, h2, l2, h3, l3;
        split_f16(v.x, h0, l0); split_f16(v.y, h1, l1);
        split_f16(v.z, h2, l2); split_f16(v.w, h3, l3);
        __half hbuf[4] = {h0, h1, h2, h3};
        __half lbuf[4] = {l0, l1, l2, l3};
        *(u64*)&hi[r * SK + c4] = *(const u64*)hbuf;
        *(u64*)&lo[r * SK + c4] = *(const u64*)lbuf;
    }
}

__global__ __launch_bounds__(256, 2) void qkv_kernel(
    const float* __restrict__ feats,
    const float* __restrict__ Wq,
    const float* __restrict__ Wk,
    const float* __restrict__ Wv,
    int N, int ntiles)
{
    char* aBuf[2] = {qkv_sm, qkv_sm + ABUF_PAIR};
    __half* sWhi = (__half*)(qkv_sm + 2 * ABUF_PAIR);
    __half* sWlo = sWhi + 192 * SK;

    const uint32_t uBase = smem_to_u32(qkv_sm);
    const uint32_t uA[2] = {uBase, uBase + ABUF_PAIR};
    const uint32_t uWhi  = uBase + 2 * ABUF_PAIR;
    const uint32_t uWlo  = uWhi + 192 * SK * 2;

    const int tid  = threadIdx.x;
    const int wid  = tid >> 5;
    const int lane = tid & 31;
    const int rg   = wid & 1;    // row group: rows rg*32 .. +32
    const int cg   = wid >> 1;   // col group: cols cg*48 .. +48

    // ---- Convert W (Wq|Wk|Wv) -> W^T [c][k] split-fp16 in smem (once) ----
    {
        const float* Ws[3] = {Wq, Wk, Wv};
        for (int e = tid; e < 12288; e += 256) {
            int c = e >> 6, k = e & 63;
            float w = Ws[c >> 6][(k << 6) + (c & 63)];
            __half hi, lo;
            split_f16(w, hi, lo);
            sWhi[c * SK + k] = hi;
            sWlo[c * SK + k] = lo;
        }
    }

    const uint32_t aoff = ((uint32_t)((rg * 32 + (lane & 15)) * SK + ((lane >> 4) << 3))) * 2;
    const uint32_t boff = ((uint32_t)((cg * 48 + (lane & 7)) * SK + (((lane >> 3) & 1) << 3))) * 2;

    // ---- Prologue: first tile into buffer 0 ----
    int tile = blockIdx.x;
    uint4 nf[4];
    if (tile < ntiles) {
        qkv_load_regs(nf, feats, tile * TILE, N, tid);
        qkv_convert_store(aBuf[0], nf, tid);
    }
    __syncthreads();

    int cur = 0;
    for (; tile < ntiles; tile += gridDim.x) {
        const int row0 = tile * TILE;
        const int tn = tile + gridDim.x;
        const bool hn = (tn < ntiles);

        if (hn) qkv_load_regs(nf, feats, tn * TILE, N, tid);

        float c[2][6][4];
#pragma unroll
        for (int rt = 0; rt < 2; rt++)
#pragma unroll
            for (int nt = 0; nt < 6; nt++)
#pragma unroll
                for (int t = 0; t < 4; t++) c[rt][nt][t] = 0.f;

        const uint32_t uAhi = uA[cur];
        const uint32_t uAlo = uAhi + ABUF_BYTES;
#pragma unroll
        for (int ks = 0; ks < 4; ks++) {
            uint32_t ahi[2][4], alo[2][4];
#pragma unroll
            for (int rt = 0; rt < 2; rt++) {
                uint32_t off = aoff + (uint32_t)(rt * 16 * SK * 2 + ks * 32);
                ldm_x4(ahi[rt], uAhi + off);
                ldm_x4(alo[rt], uAlo + off);
            }
#pragma unroll
            for (int nt = 0; nt < 6; nt++) {
                uint32_t off = boff + (uint32_t)(nt * 8 * SK * 2 + ks * 32);
                uint32_t bhi[2], blo[2];
                ldm_x2(bhi, uWhi + off);
                ldm_x2(blo, uWlo + off);
#pragma unroll
                for (int rt = 0; rt < 2; rt++) {
                    mma16816(c[rt][nt], ahi[rt], bhi);
                    mma16816(c[rt][nt], alo[rt], bhi);
                    mma16816(c[rt][nt], ahi[rt], blo);
                }
            }
        }

        if (hn) qkv_convert_store(aBuf[cur ^ 1], nf, tid);

        // ---- Epilogue: C fragments -> g_q (fp32), g_k/g_v (fp16) ----
#pragma unroll
        for (int rt = 0; rt < 2; rt++) {
            const int r0 = row0 + rg * 32 + rt * 16 + (lane >> 2);
            const int r1 = r0 + 8;
#pragma unroll
            for (int nt = 0; nt < 6; nt++) {
                const int cglob = cg * 48 + nt * 8 + ((lane & 3) << 1);
                const float* cc = c[rt][nt];
                if (cglob < 64) {
                    if (r0 < N) *(float2*)&g_q[(size_t)r0 * 64 + cglob] = make_float2(cc[0], cc[1]);
                    if (r1 < N) *(float2*)&g_q[(size_t)r1 * 64 + cglob] = make_float2(cc[2], cc[3]);
                } else if (cglob < 128) {
                    const int cl = cglob - 64;
                    if (r0 < N) *(__half2*)&g_k[(size_t)r0 * 64 + cl] = __floats2half2_rn(cc[0], cc[1]);
                    if (r1 < N) *(__half2*)&g_k[(size_t)r1 * 64 + cl] = __floats2half2_rn(cc[2], cc[3]);
                } else {
                    const int cl = cglob - 128;
                    if (r0 < N) *(__half2*)&g_v[(size_t)r0 * 64 + cl] = __floats2half2_rn(cc[0], cc[1]);
                    if (r1 < N) *(__half2*)&g_v[(size_t)r1 * 64 + cl] = __floats2half2_rn(cc[2], cc[3]);
                }
            }
        }

        cur ^= 1;
        __syncthreads();
    }
}

// ---------------------------------------------------------------------------
// Kernel 2: KNN attention + FFMA2 block-staged output projection.
// R12 changes: (a) neighbor indices re-shuffled in the v-loop instead of a
// cached idx[16] array (-16 regs), launch_bounds(256,5) -> 5 blocks/SM;
// (b) epilogue retiled to 2 rows x 4 cols: 1 LDS.128 (w) + 2 broadcast
// LDS.32 (f) per k-iter (was 1 LDS.64 + 4 LDS.32).
// ---------------------------------------------------------------------------
__global__ __launch_bounds__(256, 5) void attn_kernel(
    const int* __restrict__ knn,
    const float* __restrict__ Wo,
    const float* __restrict__ bo,
    float* __restrict__ out,
    int N)
{
    __shared__ __align__(16) float sWo[64 * 64];   // 16 KB
    __shared__ __align__(16) float sO[32 * 64];    // 8 KB staging

    const int tid = threadIdx.x;

    {
        const float4* src = (const float4*)Wo;
        float4* dst = (float4*)sWo;
#pragma unroll
        for (int t = 0; t < 4; t++) dst[tid + 256 * t] = src[tid + 256 * t];
    }

    const int g = blockIdx.x * 256 + tid;
    int n = g >> 3;
    const int h = g & 7;
    if (n >= N) n = N - 1;   // clamp: all lanes stay active for shuffles

    const int lane = tid & 31;
    const int base = lane & 24;

    const int my0 = knn[(size_t)n * 16 + h * 2];
    const int my1 = knn[(size_t)n * 16 + h * 2 + 1];

    const float* qp = g_q + (size_t)n * 64 + h * 8;
    const float4 q0 = *(const float4*)qp;
    const float4 q1 = *(const float4*)(qp + 4);

    float s[16];
#pragma unroll
    for (int k = 0; k < 16; k++) {
        int iv = (k & 1) ? my1 : my0;
        int idxk = __shfl_sync(0xffffffffu, iv, base + (k >> 1));
        uint4 raw = *(const uint4*)(g_k + (size_t)idxk * 64 + h * 8);
        float2 a0 = __half22float2(*(__half2*)&raw.x);
        float2 a1 = __half22float2(*(__half2*)&raw.y);
        float2 a2 = __half22float2(*(__half2*)&raw.z);
        float2 a3 = __half22float2(*(__half2*)&raw.w);
        float d = q0.x * a0.x + q0.y * a0.y + q0.z * a1.x + q0.w * a1.y
                + q1.x * a2.x + q1.y * a2.y + q1.z * a3.x + q1.w * a3.y;
        s[k] = d * 0.3535533905932738f;   // 1/sqrt(8)
    }

    float m = s[0];
#pragma unroll
    for (int k = 1; k < 16; k++) m = fmaxf(m, s[k]);
    float sum = 0.f;
#pragma unroll
    for (int k = 0; k < 16; k++) { s[k] = __expf(s[k] - m); sum += s[k]; }
    const float inv = 1.0f / sum;

    float o[8];
#pragma unroll
    for (int d = 0; d < 8; d++) o[d] = 0.f;
#pragma unroll
    for (int k = 0; k < 16; k++) {
        int iv = (k & 1) ? my1 : my0;
        int idxk = __shfl_sync(0xffffffffu, iv, base + (k >> 1));
        uint4 raw = *(const uint4*)(g_v + (size_t)idxk * 64 + h * 8);
        float2 a0 = __half22float2(*(__half2*)&raw.x);
        float2 a1 = __half22float2(*(__half2*)&raw.y);
        float2 a2 = __half22float2(*(__half2*)&raw.z);
        float2 a3 = __half22float2(*(__half2*)&raw.w);
        const float p = s[k];
        o[0] += p * a0.x; o[1] += p * a0.y; o[2] += p * a1.x; o[3] += p * a1.y;
        o[4] += p * a2.x; o[5] += p * a2.y; o[6] += p * a3.x; o[7] += p * a3.y;
    }

    // ---- Stage: sO[p_local][h*8 .. h*8+7] ----
    {
        const int p_local = tid >> 3;
        float* sp = &sO[p_local * 64 + h * 8];
        *(float4*)(sp)     = make_float4(o[0] * inv, o[1] * inv, o[2] * inv, o[3] * inv);
        *(float4*)(sp + 4) = make_float4(o[4] * inv, o[5] * inv, o[6] * inv, o[7] * inv);
    }
    __syncthreads();

    // ---- Block GEMM: out[32,64] = sO[32,64] @ sWo[64,64] + bo ----
    // Thread (ti, tj): rows 2ti..2ti+1, cols 4tj..4tj+3.
    const int ti = tid >> 4;   // 0..15
    const int tj = tid & 15;   // 0..15

    u64 acc[2][2];
    {
        const float4 b = *(const float4*)&bo[4 * tj];
        acc[0][0] = pack2f(b.x, b.y); acc[0][1] = pack2f(b.z, b.w);
        acc[1][0] = acc[0][0];        acc[1][1] = acc[0][1];
    }

#pragma unroll 8
    for (int i = 0; i < 64; i++) {
        ulonglong2 w = *(const ulonglong2*)&sWo[i * 64 + 4 * tj];   // LDS.128
        const float f0 = sO[(2 * ti) * 64 + i];
        const float f1 = sO[(2 * ti + 1) * 64 + i];
        const u64 fd0 = pack2f(f0, f0);
        const u64 fd1 = pack2f(f1, f1);
        fma2(acc[0][0], w.x, fd0);
        fma2(acc[0][1], w.y, fd0);
        fma2(acc[1][0], w.x, fd1);
        fma2(acc[1][1], w.y, fd1);
    }

    const int row0 = blockIdx.x * 32 + 2 * ti;
#pragma unroll
    for (int r = 0; r < 2; r++) {
        const int row = row0 + r;
        if (row < N) {
            float4 v;
            unpack2(acc[r][0], v.x, v.y);
            unpack2(acc[r][1], v.z, v.w);
            *(float4*)&out[(size_t)row * 64 + 4 * tj] = v;
        }
    }
}

// ---------------------------------------------------------------------------
extern "C" void kernel_launch(void* const* d_in, const int* in_sizes, int n_in,
                              void* d_out, int out_size)
{
    const float* feats = (const float*)d_in[0];
    const int*   knn   = (const int*)d_in[1];
    const float* Wq    = (const float*)d_in[2];
    const float* Wk    = (const float*)d_in[3];
    const float* Wv    = (const float*)d_in[4];
    const float* Wo    = (const float*)d_in[5];
    const float* bo    = (const float*)d_in[6];
    float* out = (float*)d_out;

    const int N = in_sizes[0] / CDIM;
    const int ntiles = (N + TILE - 1) / TILE;
    const int attn_blocks = (N * 8 + 255) / 256;
    // smem: 2 A buffers (hi+lo) + W hi/lo = 2*18432 + 2*192*72*2 = 92160 B
    const int qkv_smem_bytes = 2 * ABUF_PAIR + 2 * 192 * SK * 2;

    cudaFuncSetAttribute(qkv_kernel, cudaFuncAttributeMaxDynamicSharedMemorySize,
                         qkv_smem_bytes);

    int grid = 296;
    if (grid > ntiles) grid = ntiles;
    qkv_kernel<<<grid, 256, qkv_smem_bytes>>>(feats, Wq, Wk, Wv, N, ntiles);
    attn_kernel<<<attn_blocks, 256>>>(knn, Wo, bo, out, N);
}

// round 13
// speedup vs baseline: 1.0246x; 1.0246x over previous
#include <cuda_runtime.h>
#include <cuda_fp16.h>
#include <cstdint>

// Journal:
//  - tcgen05/TMEM unusable (compute_103 PTX target). HMMA (mma.sync) works.
//  - qkv: double-buffered 3-term split-fp16 HMMA (~40us, R10/R11).
//  - attn R12 (reg-diet + re-shuffle) REGRESSED: attn is L1-THROUGHPUT bound;
//    extra SHFLs on the L1/MIO pipe hurt. Reverted.
//  - attn R13: HMMA oproj epilogue, split cost OFF critical path — W split
//    2-term (once per block), attn output staged as SINGLE fp16 (4 cvt).
//    R10's failure was 16 splits+packing on the critical path; this has 4 cvt.

#define NPTS 100000
#define CDIM 64
#define TILE 64
#define SK   72   // smem row stride in halves (conflict-free ldmatrix)

// Scratch (device globals — no allocations allowed in kernel_launch)
__device__ float  g_q[NPTS * CDIM];
__device__ __half g_k[NPTS * CDIM];
__device__ __half g_v[NPTS * CDIM];

typedef unsigned long long u64;

__device__ __forceinline__ uint32_t smem_to_u32(const void* p) {
    uint32_t a;
    asm("{ .reg .u64 t; cvta.to.shared.u64 t, %1; cvt.u32.u64 %0, t; }" : "=r"(a) : "l"(p));
    return a;
}

// ---- HMMA building blocks (sm_80-era PTX, valid on compute_103) ----
__device__ __forceinline__ void ldm_x4(uint32_t* r, uint32_t addr) {
    asm volatile("ldmatrix.sync.aligned.m8n8.x4.shared.b16 {%0,%1,%2,%3}, [%4];"
                 : "=r"(r[0]), "=r"(r[1]), "=r"(r[2]), "=r"(r[3]) : "r"(addr));
}
__device__ __forceinline__ void ldm_x2(uint32_t* r, uint32_t addr) {
    asm volatile("ldmatrix.sync.aligned.m8n8.x2.shared.b16 {%0,%1}, [%2];"
                 : "=r"(r[0]), "=r"(r[1]) : "r"(addr));
}
__device__ __forceinline__ void mma16816(float* c, const uint32_t* a, const uint32_t* b) {
    asm volatile("mma.sync.aligned.m16n8k16.row.col.f32.f16.f16.f32 "
                 "{%0,%1,%2,%3}, {%4,%5,%6,%7}, {%8,%9}, {%0,%1,%2,%3};"
                 : "+f"(c[0]), "+f"(c[1]), "+f"(c[2]), "+f"(c[3])
                 : "r"(a[0]), "r"(a[1]), "r"(a[2]), "r"(a[3]), "r"(b[0]), "r"(b[1]));
}

// fp32 -> (hi, lo) fp16 split: hi + lo ≈ x with ~2^-22 relative error.
__device__ __forceinline__ void split_f16(float x, __half& hi, __half& lo) {
    hi = __float2half_rn(x);
    lo = __float2half_rn(x - __half2float(hi));
}

// ---------------------------------------------------------------------------
// Kernel 1: q/k/v projection on the tensor pipe, double-buffered A (R11).
// ---------------------------------------------------------------------------
extern __shared__ __align__(16) char qkv_sm[];

#define ABUF_BYTES (64 * SK * 2)          // one A matrix (hi or lo): 9216 B
#define ABUF_PAIR  (2 * ABUF_BYTES)       // hi+lo: 18432 B

__device__ __forceinline__ void qkv_load_regs(uint4* nf, const float* feats,
                                              int row0, int N, int tid)
{
#pragma unroll
    for (int i = 0; i < 4; i++) {
        int e = tid + (i << 8);
        int row = row0 + (e >> 4);
        nf[i] = make_uint4(0u, 0u, 0u, 0u);
        if (row < N)
            nf[i] = *(const uint4*)(feats + (size_t)row * 64 + ((e & 15) << 2));
    }
}

__device__ __forceinline__ void qkv_convert_store(char* abuf, const uint4* nf, int tid)
{
    __half* hi = (__half*)abuf;
    __half* lo = (__half*)(abuf + ABUF_BYTES);
#pragma unroll
    for (int i = 0; i < 4; i++) {
        int e = tid + (i << 8);
        int r = e >> 4, c4 = (e & 15) << 2;
        float4 v = *(const float4*)&nf[i];
        __half h0, l0, h1, l1, h2, l2, h3, l3;
        split_f16(v.x, h0, l0); split_f16(v.y, h1, l1);
        split_f16(v.z, h2, l2); split_f16(v.w, h3, l3);
        __half hbuf[4] = {h0, h1, h2, h3};
        __half lbuf[4] = {l0, l1, l2, l3};
        *(u64*)&hi[r * SK + c4] = *(const u64*)hbuf;
        *(u64*)&lo[r * SK + c4] = *(const u64*)lbuf;
    }
}

__global__ __launch_bounds__(256, 2) void qkv_kernel(
    const float* __restrict__ feats,
    const float* __restrict__ Wq,
    const float* __restrict__ Wk,
    const float* __restrict__ Wv,
    int N, int ntiles)
{
    char* aBuf[2] = {qkv_sm, qkv_sm + ABUF_PAIR};
    __half* sWhi = (__half*)(qkv_sm + 2 * ABUF_PAIR);
    __half* sWlo = sWhi + 192 * SK;

    const uint32_t uBase = smem_to_u32(qkv_sm);
    const uint32_t uA[2] = {uBase, uBase + ABUF_PAIR};
    const uint32_t uWhi  = uBase + 2 * ABUF_PAIR;
    const uint32_t uWlo  = uWhi + 192 * SK * 2;

    const int tid  = threadIdx.x;
    const int wid  = tid >> 5;
    const int lane = tid & 31;
    const int rg   = wid & 1;    // row group: rows rg*32 .. +32
    const int cg   = wid >> 1;   // col group: cols cg*48 .. +48

    // ---- Convert W (Wq|Wk|Wv) -> W^T [c][k] split-fp16 in smem (once) ----
    {
        const float* Ws[3] = {Wq, Wk, Wv};
        for (int e = tid; e < 12288; e += 256) {
            int c = e >> 6, k = e & 63;
            float w = Ws[c >> 6][(k << 6) + (c & 63)];
            __half hi, lo;
            split_f16(w, hi, lo);
            sWhi[c * SK + k] = hi;
            sWlo[c * SK + k] = lo;
        }
    }

    const uint32_t aoff = ((uint32_t)((rg * 32 + (lane & 15)) * SK + ((lane >> 4) << 3))) * 2;
    const uint32_t boff = ((uint32_t)((cg * 48 + (lane & 7)) * SK + (((lane >> 3) & 1) << 3))) * 2;

    // ---- Prologue: first tile into buffer 0 ----
    int tile = blockIdx.x;
    uint4 nf[4];
    if (tile < ntiles) {
        qkv_load_regs(nf, feats, tile * TILE, N, tid);
        qkv_convert_store(aBuf[0], nf, tid);
    }
    __syncthreads();

    int cur = 0;
    for (; tile < ntiles; tile += gridDim.x) {
        const int row0 = tile * TILE;
        const int tn = tile + gridDim.x;
        const bool hn = (tn < ntiles);

        if (hn) qkv_load_regs(nf, feats, tn * TILE, N, tid);

        float c[2][6][4];
#pragma unroll
        for (int rt = 0; rt < 2; rt++)
#pragma unroll
            for (int nt = 0; nt < 6; nt++)
#pragma unroll
                for (int t = 0; t < 4; t++) c[rt][nt][t] = 0.f;

        const uint32_t uAhi = uA[cur];
        const uint32_t uAlo = uAhi + ABUF_BYTES;
#pragma unroll
        for (int ks = 0; ks < 4; ks++) {
            uint32_t ahi[2][4], alo[2][4];
#pragma unroll
            for (int rt = 0; rt < 2; rt++) {
                uint32_t off = aoff + (uint32_t)(rt * 16 * SK * 2 + ks * 32);
                ldm_x4(ahi[rt], uAhi + off);
                ldm_x4(alo[rt], uAlo + off);
            }
#pragma unroll
            for (int nt = 0; nt < 6; nt++) {
                uint32_t off = boff + (uint32_t)(nt * 8 * SK * 2 + ks * 32);
                uint32_t bhi[2], blo[2];
                ldm_x2(bhi, uWhi + off);
                ldm_x2(blo, uWlo + off);
#pragma unroll
                for (int rt = 0; rt < 2; rt++) {
                    mma16816(c[rt][nt], ahi[rt], bhi);
                    mma16816(c[rt][nt], alo[rt], bhi);
                    mma16816(c[rt][nt], ahi[rt], blo);
                }
            }
        }

        if (hn) qkv_convert_store(aBuf[cur ^ 1], nf, tid);

        // ---- Epilogue: C fragments -> g_q (fp32), g_k/g_v (fp16) ----
#pragma unroll
        for (int rt = 0; rt < 2; rt++) {
            const int r0 = row0 + rg * 32 + rt * 16 + (lane >> 2);
            const int r1 = r0 + 8;
#pragma unroll
            for (int nt = 0; nt < 6; nt++) {
                const int cglob = cg * 48 + nt * 8 + ((lane & 3) << 1);
                const float* cc = c[rt][nt];
                if (cglob < 64) {
                    if (r0 < N) *(float2*)&g_q[(size_t)r0 * 64 + cglob] = make_float2(cc[0], cc[1]);
                    if (r1 < N) *(float2*)&g_q[(size_t)r1 * 64 + cglob] = make_float2(cc[2], cc[3]);
                } else if (cglob < 128) {
                    const int cl = cglob - 64;
                    if (r0 < N) *(__half2*)&g_k[(size_t)r0 * 64 + cl] = __floats2half2_rn(cc[0], cc[1]);
                    if (r1 < N) *(__half2*)&g_k[(size_t)r1 * 64 + cl] = __floats2half2_rn(cc[2], cc[3]);
                } else {
                    const int cl = cglob - 128;
                    if (r0 < N) *(__half2*)&g_v[(size_t)r0 * 64 + cl] = __floats2half2_rn(cc[0], cc[1]);
                    if (r1 < N) *(__half2*)&g_v[(size_t)r1 * 64 + cl] = __floats2half2_rn(cc[2], cc[3]);
                }
            }
        }

        cur ^= 1;
        __syncthreads();
    }
}

// ---------------------------------------------------------------------------
// Kernel 2: KNN attention (R11 gather, verbatim) + HMMA oproj epilogue.
// W split 2-term (off critical path); attn output staged single fp16.
// Per warp: 4 ks x (1 ldm_x4 A + 2 nt x 2 ldm_x2 B) + 16 mma.
// ---------------------------------------------------------------------------
__global__ __launch_bounds__(256) void attn_kernel(
    const int* __restrict__ knn,
    const float* __restrict__ Wo,
    const float* __restrict__ bo,
    float* __restrict__ out,
    int N)
{
    __shared__ __align__(16) __half sWohi[64 * SK];   // Wo^T hi: [n][k]
    __shared__ __align__(16) __half sWolo[64 * SK];   // Wo^T lo
    __shared__ __align__(16) __half sOh[32 * SK];     // staged attn out (fp16)

    const int tid = threadIdx.x;

    // ---- Convert Wo -> Wo^T split-fp16 (once, off critical path) ----
    for (int e = tid; e < 4096; e += 256) {
        int k = e >> 6, n = e & 63;
        __half hi, lo;
        split_f16(Wo[e], hi, lo);
        sWohi[n * SK + k] = hi;
        sWolo[n * SK + k] = lo;
    }

    const int g = blockIdx.x * 256 + tid;
    int n = g >> 3;
    const int h = g & 7;
    if (n >= N) n = N - 1;   // clamp: all lanes stay active for shuffles

    const int lane = tid & 31;
    const int base = lane & 24;

    const int my0 = knn[(size_t)n * 16 + h * 2];
    const int my1 = knn[(size_t)n * 16 + h * 2 + 1];

    const float* qp = g_q + (size_t)n * 64 + h * 8;
    const float4 q0 = *(const float4*)qp;
    const float4 q1 = *(const float4*)(qp + 4);

    int   idx[16];
    float s[16];
#pragma unroll
    for (int k = 0; k < 16; k++) {
        int v = (k & 1) ? my1 : my0;
        idx[k] = __shfl_sync(0xffffffffu, v, base + (k >> 1));
    }

#pragma unroll
    for (int k = 0; k < 16; k++) {
        uint4 raw = *(const uint4*)(g_k + (size_t)idx[k] * 64 + h * 8);
        float2 a0 = __half22float2(*(__half2*)&raw.x);
        float2 a1 = __half22float2(*(__half2*)&raw.y);
        float2 a2 = __half22float2(*(__half2*)&raw.z);
        float2 a3 = __half22float2(*(__half2*)&raw.w);
        float d = q0.x * a0.x + q0.y * a0.y + q0.z * a1.x + q0.w * a1.y
                + q1.x * a2.x + q1.y * a2.y + q1.z * a3.x + q1.w * a3.y;
        s[k] = d * 0.3535533905932738f;   // 1/sqrt(8)
    }

    float m = s[0];
#pragma unroll
    for (int k = 1; k < 16; k++) m = fmaxf(m, s[k]);
    float sum = 0.f;
#pragma unroll
    for (int k = 0; k < 16; k++) { s[k] = __expf(s[k] - m); sum += s[k]; }
    const float inv = 1.0f / sum;

    float o[8];
#pragma unroll
    for (int d = 0; d < 8; d++) o[d] = 0.f;
#pragma unroll
    for (int k = 0; k < 16; k++) {
        uint4 raw = *(const uint4*)(g_v + (size_t)idx[k] * 64 + h * 8);
        float2 a0 = __half22float2(*(__half2*)&raw.x);
        float2 a1 = __half22float2(*(__half2*)&raw.y);
        float2 a2 = __half22float2(*(__half2*)&raw.z);
        float2 a3 = __half22float2(*(__half2*)&raw.w);
        const float p = s[k];
        o[0] += p * a0.x; o[1] += p * a0.y; o[2] += p * a1.x; o[3] += p * a1.y;
        o[4] += p * a2.x; o[5] += p * a2.y; o[6] += p * a3.x; o[7] += p * a3.y;
    }

    // ---- Stage single fp16: sOh[p_local][h*8 .. h*8+7] (4 cvt + 1 STS.128) ----
    {
        const int p_local = tid >> 3;
        union { uint4 u; __half2 h2[4]; } sh;
#pragma unroll
        for (int i = 0; i < 4; i++)
            sh.h2[i] = __floats2half2_rn(o[2 * i] * inv, o[2 * i + 1] * inv);
        *(uint4*)&sOh[p_local * SK + h * 8] = sh.u;
    }
    __syncthreads();

    // ---- HMMA oproj: out[32,64] = sOh @ (Wohi + Wolo) + bo ----
    const int wid = tid >> 5;
    const int mt  = wid & 1;           // m-tile (16 rows)
    const int nt0 = (wid >> 1) << 1;   // first of 2 n-tiles (8 cols each)

    const uint32_t uOh   = smem_to_u32(sOh);
    const uint32_t uWohi = smem_to_u32(sWohi);
    const uint32_t uWolo = smem_to_u32(sWolo);

    const uint32_t aoff = ((uint32_t)((mt * 16 + (lane & 15)) * SK + ((lane >> 4) << 3))) * 2;

    float c[2][4];
#pragma unroll
    for (int j = 0; j < 2; j++)
#pragma unroll
        for (int t = 0; t < 4; t++) c[j][t] = 0.f;

#pragma unroll
    for (int ks = 0; ks < 4; ks++) {
        uint32_t a[4];
        ldm_x4(a, uOh + aoff + ks * 32);
#pragma unroll
        for (int j = 0; j < 2; j++) {
            uint32_t boff = ((uint32_t)(((nt0 + j) * 8 + (lane & 7)) * SK +
                                        (((lane >> 3) & 1) << 3))) * 2 + ks * 32;
            uint32_t bhi[2], blo[2];
            ldm_x2(bhi, uWohi + boff);
            ldm_x2(blo, uWolo + boff);
            mma16816(c[j], a, bhi);
            mma16816(c[j], a, blo);
        }
    }

    // ---- Write with bias ----
    const int r0 = blockIdx.x * 32 + mt * 16 + (lane >> 2);
    const int r1 = r0 + 8;
#pragma unroll
    for (int j = 0; j < 2; j++) {
        const int cc = (nt0 + j) * 8 + ((lane & 3) << 1);
        const float2 b = *(const float2*)&bo[cc];
        if (r0 < N) *(float2*)&out[(size_t)r0 * 64 + cc] =
            make_float2(c[j][0] + b.x, c[j][1] + b.y);
        if (r1 < N) *(float2*)&out[(size_t)r1 * 64 + cc] =
            make_float2(c[j][2] + b.x, c[j][3] + b.y);
    }
}

// ---------------------------------------------------------------------------
extern "C" void kernel_launch(void* const* d_in, const int* in_sizes, int n_in,
                              void* d_out, int out_size)
{
    const float* feats = (const float*)d_in[0];
    const int*   knn   = (const int*)d_in[1];
    const float* Wq    = (const float*)d_in[2];
    const float* Wk    = (const float*)d_in[3];
    const float* Wv    = (const float*)d_in[4];
    const float* Wo    = (const float*)d_in[5];
    const float* bo    = (const float*)d_in[6];
    float* out = (float*)d_out;

    const int N = in_sizes[0] / CDIM;
    const int ntiles = (N + TILE - 1) / TILE;
    const int attn_blocks = (N * 8 + 255) / 256;
    // smem: 2 A buffers (hi+lo) + W hi/lo = 2*18432 + 2*192*72*2 = 92160 B
    const int qkv_smem_bytes = 2 * ABUF_PAIR + 2 * 192 * SK * 2;

    cudaFuncSetAttribute(qkv_kernel, cudaFuncAttributeMaxDynamicSharedMemorySize,
                         qkv_smem_bytes);

    int grid = 296;
    if (grid > ntiles) grid = ntiles;
    qkv_kernel<<<grid, 256, qkv_smem_bytes>>>(feats, Wq, Wk, Wv, N, ntiles);
    attn_kernel<<<attn_blocks, 256>>>(knn, Wo, bo, out, N);
}

// round 14
// speedup vs baseline: 1.1245x; 1.0975x over previous
#include <cuda_runtime.h>
#include <cuda_fp16.h>
#include <cstdint>

// Journal:
//  - tcgen05/TMEM unusable (compute_103 PTX target). HMMA (mma.sync) works.
//  - attn: gather phase sits at the L2 gather ceiling (~410MB / ~8TB/s);
//    FFMA2 block-staged epilogue hides under it. TWO HMMA-epilogue attempts
//    regressed (R10 +8.7us, R13 +7.3us) — epilogue is CLOSED at R11 form.
//  - qkv R14: 2-term split (feats single fp16, W split hi/lo) — W is
//    fp32-equivalent, feats carries ~3.5e-4 fp16 quantization. MACs -33%,
//    per-tile convert halved. Expected rel_err ~4.5e-4 (<1e-3).

#define NPTS 100000
#define CDIM 64
#define TILE 64
#define SK   72   // smem row stride in halves (conflict-free ldmatrix)

// Scratch (device globals — no allocations allowed in kernel_launch)
__device__ float  g_q[NPTS * CDIM];
__device__ __half g_k[NPTS * CDIM];
__device__ __half g_v[NPTS * CDIM];

typedef unsigned long long u64;

__device__ __forceinline__ uint32_t smem_to_u32(const void* p) {
    uint32_t a;
    asm("{ .reg .u64 t; cvta.to.shared.u64 t, %1; cvt.u32.u64 %0, t; }" : "=r"(a) : "l"(p));
    return a;
}
__device__ __forceinline__ void fma2(u64& d, u64 a, u64 b) {
    asm("fma.rn.f32x2 %0, %1, %2, %0;" : "+l"(d) : "l"(a), "l"(b));
}
__device__ __forceinline__ void unpack2(u64 v, float& lo, float& hi) {
    asm("mov.b64 {%0, %1}, %2;" : "=f"(lo), "=f"(hi) : "l"(v));
}
__device__ __forceinline__ u64 pack2f(float lo, float hi) {
    u64 r;
    asm("mov.b64 %0, {%1, %2};" : "=l"(r) : "f"(lo), "f"(hi));
    return r;
}

// ---- HMMA building blocks (sm_80-era PTX, valid on compute_103) ----
__device__ __forceinline__ void ldm_x4(uint32_t* r, uint32_t addr) {
    asm volatile("ldmatrix.sync.aligned.m8n8.x4.shared.b16 {%0,%1,%2,%3}, [%4];"
                 : "=r"(r[0]), "=r"(r[1]), "=r"(r[2]), "=r"(r[3]) : "r"(addr));
}
__device__ __forceinline__ void ldm_x2(uint32_t* r, uint32_t addr) {
    asm volatile("ldmatrix.sync.aligned.m8n8.x2.shared.b16 {%0,%1}, [%2];"
                 : "=r"(r[0]), "=r"(r[1]) : "r"(addr));
}
__device__ __forceinline__ void mma16816(float* c, const uint32_t* a, const uint32_t* b) {
    asm volatile("mma.sync.aligned.m16n8k16.row.col.f32.f16.f16.f32 "
                 "{%0,%1,%2,%3}, {%4,%5,%6,%7}, {%8,%9}, {%0,%1,%2,%3};"
                 : "+f"(c[0]), "+f"(c[1]), "+f"(c[2]), "+f"(c[3])
                 : "r"(a[0]), "r"(a[1]), "r"(a[2]), "r"(a[3]), "r"(b[0]), "r"(b[1]));
}

// fp32 -> (hi, lo) fp16 split: hi + lo ≈ x with ~2^-22 relative error.
__device__ __forceinline__ void split_f16(float x, __half& hi, __half& lo) {
    hi = __float2half_rn(x);
    lo = __float2half_rn(x - __half2float(hi));
}

// ---------------------------------------------------------------------------
// Kernel 1: q/k/v projection, tensor pipe, double-buffered A.
// D[64,192] per tile = fp16(feats)[64,64] @ (Whi + Wlo)[64,192].
// Per warp per tile: 8 ldm_x4 (A) + 48 ldm_x2 (B) + 96 mma.
// ---------------------------------------------------------------------------
extern __shared__ __align__(16) char qkv_sm[];

#define ABUF_BYTES (64 * SK * 2)          // one fp16 A tile: 9216 B

__device__ __forceinline__ void qkv_load_regs(uint4* nf, const float* feats,
                                              int row0, int N, int tid)
{
#pragma unroll
    for (int i = 0; i < 4; i++) {
        int e = tid + (i << 8);
        int row = row0 + (e >> 4);
        nf[i] = make_uint4(0u, 0u, 0u, 0u);
        if (row < N)
            nf[i] = *(const uint4*)(feats + (size_t)row * 64 + ((e & 15) << 2));
    }
}

__device__ __forceinline__ void qkv_convert_store(char* abuf, const uint4* nf, int tid)
{
    __half* hi = (__half*)abuf;
#pragma unroll
    for (int i = 0; i < 4; i++) {
        int e = tid + (i << 8);
        int r = e >> 4, c4 = (e & 15) << 2;
        float4 v = *(const float4*)&nf[i];
        __half2 hb[2] = {__floats2half2_rn(v.x, v.y), __floats2half2_rn(v.z, v.w)};
        *(u64*)&hi[r * SK + c4] = *(const u64*)hb;
    }
}

__global__ __launch_bounds__(256, 2) void qkv_kernel(
    const float* __restrict__ feats,
    const float* __restrict__ Wq,
    const float* __restrict__ Wk,
    const float* __restrict__ Wv,
    int N, int ntiles)
{
    char* aBuf[2] = {qkv_sm, qkv_sm + ABUF_BYTES};
    __half* sWhi = (__half*)(qkv_sm + 2 * ABUF_BYTES);
    __half* sWlo = sWhi + 192 * SK;

    const uint32_t uBase = smem_to_u32(qkv_sm);
    const uint32_t uA[2] = {uBase, uBase + ABUF_BYTES};
    const uint32_t uWhi  = uBase + 2 * ABUF_BYTES;
    const uint32_t uWlo  = uWhi + 192 * SK * 2;

    const int tid  = threadIdx.x;
    const int wid  = tid >> 5;
    const int lane = tid & 31;
    const int rg   = wid & 1;    // row group: rows rg*32 .. +32
    const int cg   = wid >> 1;   // col group: cols cg*48 .. +48

    // ---- Convert W (Wq|Wk|Wv) -> W^T [c][k] split-fp16 in smem (once) ----
    {
        const float* Ws[3] = {Wq, Wk, Wv};
        for (int e = tid; e < 12288; e += 256) {
            int c = e >> 6, k = e & 63;
            float w = Ws[c >> 6][(k << 6) + (c & 63)];
            __half hi, lo;
            split_f16(w, hi, lo);
            sWhi[c * SK + k] = hi;
            sWlo[c * SK + k] = lo;
        }
    }

    const uint32_t aoff = ((uint32_t)((rg * 32 + (lane & 15)) * SK + ((lane >> 4) << 3))) * 2;
    const uint32_t boff = ((uint32_t)((cg * 48 + (lane & 7)) * SK + (((lane >> 3) & 1) << 3))) * 2;

    // ---- Prologue: first tile into buffer 0 ----
    int tile = blockIdx.x;
    uint4 nf[4];
    if (tile < ntiles) {
        qkv_load_regs(nf, feats, tile * TILE, N, tid);
        qkv_convert_store(aBuf[0], nf, tid);
    }
    __syncthreads();

    int cur = 0;
    for (; tile < ntiles; tile += gridDim.x) {
        const int row0 = tile * TILE;
        const int tn = tile + gridDim.x;
        const bool hn = (tn < ntiles);

        if (hn) qkv_load_regs(nf, feats, tn * TILE, N, tid);

        float c[2][6][4];
#pragma unroll
        for (int rt = 0; rt < 2; rt++)
#pragma unroll
            for (int nt = 0; nt < 6; nt++)
#pragma unroll
                for (int t = 0; t < 4; t++) c[rt][nt][t] = 0.f;

        const uint32_t uAc = uA[cur];
#pragma unroll
        for (int ks = 0; ks < 4; ks++) {
            uint32_t a[2][4];
#pragma unroll
            for (int rt = 0; rt < 2; rt++) {
                uint32_t off = aoff + (uint32_t)(rt * 16 * SK * 2 + ks * 32);
                ldm_x4(a[rt], uAc + off);
            }
#pragma unroll
            for (int nt = 0; nt < 6; nt++) {
                uint32_t off = boff + (uint32_t)(nt * 8 * SK * 2 + ks * 32);
                uint32_t bhi[2], blo[2];
                ldm_x2(bhi, uWhi + off);
                ldm_x2(blo, uWlo + off);
#pragma unroll
                for (int rt = 0; rt < 2; rt++) {
                    mma16816(c[rt][nt], a[rt], bhi);
                    mma16816(c[rt][nt], a[rt], blo);
                }
            }
        }

        if (hn) qkv_convert_store(aBuf[cur ^ 1], nf, tid);

        // ---- Epilogue: C fragments -> g_q (fp32), g_k/g_v (fp16) ----
#pragma unroll
        for (int rt = 0; rt < 2; rt++) {
            const int r0 = row0 + rg * 32 + rt * 16 + (lane >> 2);
            const int r1 = r0 + 8;
#pragma unroll
            for (int nt = 0; nt < 6; nt++) {
                const int cglob = cg * 48 + nt * 8 + ((lane & 3) << 1);
                const float* cc = c[rt][nt];
                if (cglob < 64) {
                    if (r0 < N) *(float2*)&g_q[(size_t)r0 * 64 + cglob] = make_float2(cc[0], cc[1]);
                    if (r1 < N) *(float2*)&g_q[(size_t)r1 * 64 + cglob] = make_float2(cc[2], cc[3]);
                } else if (cglob < 128) {
                    const int cl = cglob - 64;
                    if (r0 < N) *(__half2*)&g_k[(size_t)r0 * 64 + cl] = __floats2half2_rn(cc[0], cc[1]);
                    if (r1 < N) *(__half2*)&g_k[(size_t)r1 * 64 + cl] = __floats2half2_rn(cc[2], cc[3]);
                } else {
                    const int cl = cglob - 128;
                    if (r0 < N) *(__half2*)&g_v[(size_t)r0 * 64 + cl] = __floats2half2_rn(cc[0], cc[1]);
                    if (r1 < N) *(__half2*)&g_v[(size_t)r1 * 64 + cl] = __floats2half2_rn(cc[2], cc[3]);
                }
            }
        }

        cur ^= 1;
        __syncthreads();
    }
}

// ---------------------------------------------------------------------------
// Kernel 2: KNN attention + FFMA2 block-staged output projection (R11 exact).
// ---------------------------------------------------------------------------
__global__ __launch_bounds__(256) void attn_kernel(
    const int* __restrict__ knn,
    const float* __restrict__ Wo,
    const float* __restrict__ bo,
    float* __restrict__ out,
    int N)
{
    __shared__ __align__(16) float sWo[64 * 64];   // 16 KB
    __shared__ __align__(16) float sO[32 * 64];    // 8 KB staging

    const int tid = threadIdx.x;

    {
        const float4* src = (const float4*)Wo;
        float4* dst = (float4*)sWo;
#pragma unroll
        for (int t = 0; t < 4; t++) dst[tid + 256 * t] = src[tid + 256 * t];
    }

    const int g = blockIdx.x * 256 + tid;
    int n = g >> 3;
    const int h = g & 7;
    if (n >= N) n = N - 1;   // clamp: all lanes stay active for shuffles

    const int lane = tid & 31;
    const int base = lane & 24;

    const int my0 = knn[(size_t)n * 16 + h * 2];
    const int my1 = knn[(size_t)n * 16 + h * 2 + 1];

    const float* qp = g_q + (size_t)n * 64 + h * 8;
    const float4 q0 = *(const float4*)qp;
    const float4 q1 = *(const float4*)(qp + 4);

    int   idx[16];
    float s[16];
#pragma unroll
    for (int k = 0; k < 16; k++) {
        int v = (k & 1) ? my1 : my0;
        idx[k] = __shfl_sync(0xffffffffu, v, base + (k >> 1));
    }

#pragma unroll
    for (int k = 0; k < 16; k++) {
        uint4 raw = *(const uint4*)(g_k + (size_t)idx[k] * 64 + h * 8);
        float2 a0 = __half22float2(*(__half2*)&raw.x);
        float2 a1 = __half22float2(*(__half2*)&raw.y);
        float2 a2 = __half22float2(*(__half2*)&raw.z);
        float2 a3 = __half22float2(*(__half2*)&raw.w);
        float d = q0.x * a0.x + q0.y * a0.y + q0.z * a1.x + q0.w * a1.y
                + q1.x * a2.x + q1.y * a2.y + q1.z * a3.x + q1.w * a3.y;
        s[k] = d * 0.3535533905932738f;   // 1/sqrt(8)
    }

    float m = s[0];
#pragma unroll
    for (int k = 1; k < 16; k++) m = fmaxf(m, s[k]);
    float sum = 0.f;
#pragma unroll
    for (int k = 0; k < 16; k++) { s[k] = __expf(s[k] - m); sum += s[k]; }
    const float inv = 1.0f / sum;

    float o[8];
#pragma unroll
    for (int d = 0; d < 8; d++) o[d] = 0.f;
#pragma unroll
    for (int k = 0; k < 16; k++) {
        uint4 raw = *(const uint4*)(g_v + (size_t)idx[k] * 64 + h * 8);
        float2 a0 = __half22float2(*(__half2*)&raw.x);
        float2 a1 = __half22float2(*(__half2*)&raw.y);
        float2 a2 = __half22float2(*(__half2*)&raw.z);
        float2 a3 = __half22float2(*(__half2*)&raw.w);
        const float p = s[k];
        o[0] += p * a0.x; o[1] += p * a0.y; o[2] += p * a1.x; o[3] += p * a1.y;
        o[4] += p * a2.x; o[5] += p * a2.y; o[6] += p * a3.x; o[7] += p * a3.y;
    }

    {
        const int p_local = tid >> 3;
        float* sp = &sO[p_local * 64 + h * 8];
        *(float4*)(sp)     = make_float4(o[0] * inv, o[1] * inv, o[2] * inv, o[3] * inv);
        *(float4*)(sp + 4) = make_float4(o[4] * inv, o[5] * inv, o[6] * inv, o[7] * inv);
    }
    __syncthreads();

    // ---- Block GEMM: out[32,64] = sO[32,64] @ sWo[64,64] + bo ----
    const int ty = tid >> 5;   // 0..7 : 4-row group
    const int tx = tid & 31;   // col pair

    u64 acc[4];
    {
        const float b0 = bo[2 * tx];
        const float b1 = bo[2 * tx + 1];
#pragma unroll
        for (int r = 0; r < 4; r++) acc[r] = pack2f(b0, b1);
    }

#pragma unroll 8
    for (int i = 0; i < 64; i++) {
        u64 w = *(const u64*)&sWo[i * 64 + 2 * tx];
#pragma unroll
        for (int r = 0; r < 4; r++) {
            float fv = sO[(ty * 4 + r) * 64 + i];
            fma2(acc[r], w, pack2f(fv, fv));
        }
    }

    const int row_base = blockIdx.x * 32 + ty * 4;
#pragma unroll
    for (int r = 0; r < 4; r++) {
        int row = row_base + r;
        if (row < N) {
            float2 v;
            unpack2(acc[r], v.x, v.y);
            *(float2*)&out[(size_t)row * 64 + 2 * tx] = v;
        }
    }
}

// ---------------------------------------------------------------------------
extern "C" void kernel_launch(void* const* d_in, const int* in_sizes, int n_in,
                              void* d_out, int out_size)
{
    const float* feats = (const float*)d_in[0];
    const int*   knn   = (const int*)d_in[1];
    const float* Wq    = (const float*)d_in[2];
    const float* Wk    = (const float*)d_in[3];
    const float* Wv    = (const float*)d_in[4];
    const float* Wo    = (const float*)d_in[5];
    const float* bo    = (const float*)d_in[6];
    float* out = (float*)d_out;

    const int N = in_sizes[0] / CDIM;
    const int ntiles = (N + TILE - 1) / TILE;
    const int attn_blocks = (N * 8 + 255) / 256;
    // smem: 2 fp16 A buffers + W hi/lo = 2*9216 + 2*192*72*2 = 73728 B
    const int qkv_smem_bytes = 2 * ABUF_BYTES + 2 * 192 * SK * 2;

    cudaFuncSetAttribute(qkv_kernel, cudaFuncAttributeMaxDynamicSharedMemorySize,
                         qkv_smem_bytes);

    int grid = 296;
    if (grid > ntiles) grid = ntiles;
    qkv_kernel<<<grid, 256, qkv_smem_bytes>>>(feats, Wq, Wk, Wv, N, ntiles);
    attn_kernel<<<attn_blocks, 256>>>(knn, Wo, bo, out, N);
}

// round 15
// speedup vs baseline: 1.1731x; 1.0433x over previous
#include <cuda_runtime.h>
#include <cuda_fp16.h>
#include <cstdint>

// Journal:
//  - tcgen05/TMEM unusable (compute_103 PTX target). HMMA (mma.sync) works.
//  - attn: gather at L2/latency equilibrium; FFMA2 block-staged epilogue
//    hides under it. Two HMMA-epilogue attempts regressed. CLOSED at R11.
//  - qkv: tensor-throughput bound; MAC count -> time is linear (calibrated:
//    3-term ~40us, 2-term ~33us). R15: 1-term (pure fp16 W).
//  - Error model calibrated: R14 predicted 4.5e-4, measured 4.34e-4.
//    R15 predicts ~5.5e-4 (fp16 k/v (+) feats quant (+) W quant) < 1e-3.

#define NPTS 100000
#define CDIM 64
#define TILE 64
#define SK   72   // smem row stride in halves (conflict-free ldmatrix)

// Scratch (device globals — no allocations allowed in kernel_launch)
__device__ float  g_q[NPTS * CDIM];
__device__ __half g_k[NPTS * CDIM];
__device__ __half g_v[NPTS * CDIM];

typedef unsigned long long u64;

__device__ __forceinline__ uint32_t smem_to_u32(const void* p) {
    uint32_t a;
    asm("{ .reg .u64 t; cvta.to.shared.u64 t, %1; cvt.u32.u64 %0, t; }" : "=r"(a) : "l"(p));
    return a;
}
__device__ __forceinline__ void fma2(u64& d, u64 a, u64 b) {
    asm("fma.rn.f32x2 %0, %1, %2, %0;" : "+l"(d) : "l"(a), "l"(b));
}
__device__ __forceinline__ void unpack2(u64 v, float& lo, float& hi) {
    asm("mov.b64 {%0, %1}, %2;" : "=f"(lo), "=f"(hi) : "l"(v));
}
__device__ __forceinline__ u64 pack2f(float lo, float hi) {
    u64 r;
    asm("mov.b64 %0, {%1, %2};" : "=l"(r) : "f"(lo), "f"(hi));
    return r;
}

// ---- HMMA building blocks (sm_80-era PTX, valid on compute_103) ----
__device__ __forceinline__ void ldm_x4(uint32_t* r, uint32_t addr) {
    asm volatile("ldmatrix.sync.aligned.m8n8.x4.shared.b16 {%0,%1,%2,%3}, [%4];"
                 : "=r"(r[0]), "=r"(r[1]), "=r"(r[2]), "=r"(r[3]) : "r"(addr));
}
__device__ __forceinline__ void ldm_x2(uint32_t* r, uint32_t addr) {
    asm volatile("ldmatrix.sync.aligned.m8n8.x2.shared.b16 {%0,%1}, [%2];"
                 : "=r"(r[0]), "=r"(r[1]) : "r"(addr));
}
__device__ __forceinline__ void mma16816(float* c, const uint32_t* a, const uint32_t* b) {
    asm volatile("mma.sync.aligned.m16n8k16.row.col.f32.f16.f16.f32 "
                 "{%0,%1,%2,%3}, {%4,%5,%6,%7}, {%8,%9}, {%0,%1,%2,%3};"
                 : "+f"(c[0]), "+f"(c[1]), "+f"(c[2]), "+f"(c[3])
                 : "r"(a[0]), "r"(a[1]), "r"(a[2]), "r"(a[3]), "r"(b[0]), "r"(b[1]));
}

// ---------------------------------------------------------------------------
// Kernel 1: q/k/v projection, tensor pipe, double-buffered A, 1-term fp16.
// D[64,192] per tile = fp16(feats)[64,64] @ fp16(Wq|Wk|Wv)[64,192].
// Per warp per tile: 8 ldm_x4 (A) + 24 ldm_x2 (B) + 48 mma.
// ---------------------------------------------------------------------------
extern __shared__ __align__(16) char qkv_sm[];

#define ABUF_BYTES (64 * SK * 2)          // one fp16 A tile: 9216 B

__device__ __forceinline__ void qkv_load_regs(uint4* nf, const float* feats,
                                              int row0, int N, int tid)
{
#pragma unroll
    for (int i = 0; i < 4; i++) {
        int e = tid + (i << 8);
        int row = row0 + (e >> 4);
        nf[i] = make_uint4(0u, 0u, 0u, 0u);
        if (row < N)
            nf[i] = *(const uint4*)(feats + (size_t)row * 64 + ((e & 15) << 2));
    }
}

__device__ __forceinline__ void qkv_convert_store(char* abuf, const uint4* nf, int tid)
{
    __half* hi = (__half*)abuf;
#pragma unroll
    for (int i = 0; i < 4; i++) {
        int e = tid + (i << 8);
        int r = e >> 4, c4 = (e & 15) << 2;
        float4 v = *(const float4*)&nf[i];
        __half2 hb[2] = {__floats2half2_rn(v.x, v.y), __floats2half2_rn(v.z, v.w)};
        *(u64*)&hi[r * SK + c4] = *(const u64*)hb;
    }
}

__global__ __launch_bounds__(256, 2) void qkv_kernel(
    const float* __restrict__ feats,
    const float* __restrict__ Wq,
    const float* __restrict__ Wk,
    const float* __restrict__ Wv,
    int N, int ntiles)
{
    char* aBuf[2] = {qkv_sm, qkv_sm + ABUF_BYTES};
    __half* sW = (__half*)(qkv_sm + 2 * ABUF_BYTES);   // W^T fp16: [c][k]

    const uint32_t uBase = smem_to_u32(qkv_sm);
    const uint32_t uA[2] = {uBase, uBase + ABUF_BYTES};
    const uint32_t uW    = uBase + 2 * ABUF_BYTES;

    const int tid  = threadIdx.x;
    const int wid  = tid >> 5;
    const int lane = tid & 31;
    const int rg   = wid & 1;    // row group: rows rg*32 .. +32
    const int cg   = wid >> 1;   // col group: cols cg*48 .. +48

    // ---- Convert W (Wq|Wk|Wv) -> W^T [c][k] fp16 in smem (once) ----
    {
        const float* Ws[3] = {Wq, Wk, Wv};
        for (int e = tid; e < 12288; e += 256) {
            int c = e >> 6, k = e & 63;
            sW[c * SK + k] = __float2half_rn(Ws[c >> 6][(k << 6) + (c & 63)]);
        }
    }

    const uint32_t aoff = ((uint32_t)((rg * 32 + (lane & 15)) * SK + ((lane >> 4) << 3))) * 2;
    const uint32_t boff = ((uint32_t)((cg * 48 + (lane & 7)) * SK + (((lane >> 3) & 1) << 3))) * 2;

    // ---- Prologue: first tile into buffer 0 ----
    int tile = blockIdx.x;
    uint4 nf[4];
    if (tile < ntiles) {
        qkv_load_regs(nf, feats, tile * TILE, N, tid);
        qkv_convert_store(aBuf[0], nf, tid);
    }
    __syncthreads();

    int cur = 0;
    for (; tile < ntiles; tile += gridDim.x) {
        const int row0 = tile * TILE;
        const int tn = tile + gridDim.x;
        const bool hn = (tn < ntiles);

        if (hn) qkv_load_regs(nf, feats, tn * TILE, N, tid);

        float c[2][6][4];
#pragma unroll
        for (int rt = 0; rt < 2; rt++)
#pragma unroll
            for (int nt = 0; nt < 6; nt++)
#pragma unroll
                for (int t = 0; t < 4; t++) c[rt][nt][t] = 0.f;

        const uint32_t uAc = uA[cur];
#pragma unroll
        for (int ks = 0; ks < 4; ks++) {
            uint32_t a[2][4];
#pragma unroll
            for (int rt = 0; rt < 2; rt++) {
                uint32_t off = aoff + (uint32_t)(rt * 16 * SK * 2 + ks * 32);
                ldm_x4(a[rt], uAc + off);
            }
#pragma unroll
            for (int nt = 0; nt < 6; nt++) {
                uint32_t off = boff + (uint32_t)(nt * 8 * SK * 2 + ks * 32);
                uint32_t b[2];
                ldm_x2(b, uW + off);
#pragma unroll
                for (int rt = 0; rt < 2; rt++)
                    mma16816(c[rt][nt], a[rt], b);
            }
        }

        if (hn) qkv_convert_store(aBuf[cur ^ 1], nf, tid);

        // ---- Epilogue: C fragments -> g_q (fp32), g_k/g_v (fp16) ----
#pragma unroll
        for (int rt = 0; rt < 2; rt++) {
            const int r0 = row0 + rg * 32 + rt * 16 + (lane >> 2);
            const int r1 = r0 + 8;
#pragma unroll
            for (int nt = 0; nt < 6; nt++) {
                const int cglob = cg * 48 + nt * 8 + ((lane & 3) << 1);
                const float* cc = c[rt][nt];
                if (cglob < 64) {
                    if (r0 < N) *(float2*)&g_q[(size_t)r0 * 64 + cglob] = make_float2(cc[0], cc[1]);
                    if (r1 < N) *(float2*)&g_q[(size_t)r1 * 64 + cglob] = make_float2(cc[2], cc[3]);
                } else if (cglob < 128) {
                    const int cl = cglob - 64;
                    if (r0 < N) *(__half2*)&g_k[(size_t)r0 * 64 + cl] = __floats2half2_rn(cc[0], cc[1]);
                    if (r1 < N) *(__half2*)&g_k[(size_t)r1 * 64 + cl] = __floats2half2_rn(cc[2], cc[3]);
                } else {
                    const int cl = cglob - 128;
                    if (r0 < N) *(__half2*)&g_v[(size_t)r0 * 64 + cl] = __floats2half2_rn(cc[0], cc[1]);
                    if (r1 < N) *(__half2*)&g_v[(size_t)r1 * 64 + cl] = __floats2half2_rn(cc[2], cc[3]);
                }
            }
        }

        cur ^= 1;
        __syncthreads();
    }
}

// ---------------------------------------------------------------------------
// Kernel 2: KNN attention + FFMA2 block-staged output projection (R11 exact).
// ---------------------------------------------------------------------------
__global__ __launch_bounds__(256) void attn_kernel(
    const int* __restrict__ knn,
    const float* __restrict__ Wo,
    const float* __restrict__ bo,
    float* __restrict__ out,
    int N)
{
    __shared__ __align__(16) float sWo[64 * 64];   // 16 KB
    __shared__ __align__(16) float sO[32 * 64];    // 8 KB staging

    const int tid = threadIdx.x;

    {
        const float4* src = (const float4*)Wo;
        float4* dst = (float4*)sWo;
#pragma unroll
        for (int t = 0; t < 4; t++) dst[tid + 256 * t] = src[tid + 256 * t];
    }

    const int g = blockIdx.x * 256 + tid;
    int n = g >> 3;
    const int h = g & 7;
    if (n >= N) n = N - 1;   // clamp: all lanes stay active for shuffles

    const int lane = tid & 31;
    const int base = lane & 24;

    const int my0 = knn[(size_t)n * 16 + h * 2];
    const int my1 = knn[(size_t)n * 16 + h * 2 + 1];

    const float* qp = g_q + (size_t)n * 64 + h * 8;
    const float4 q0 = *(const float4*)qp;
    const float4 q1 = *(const float4*)(qp + 4);

    int   idx[16];
    float s[16];
#pragma unroll
    for (int k = 0; k < 16; k++) {
        int v = (k & 1) ? my1 : my0;
        idx[k] = __shfl_sync(0xffffffffu, v, base + (k >> 1));
    }

#pragma unroll
    for (int k = 0; k < 16; k++) {
        uint4 raw = *(const uint4*)(g_k + (size_t)idx[k] * 64 + h * 8);
        float2 a0 = __half22float2(*(__half2*)&raw.x);
        float2 a1 = __half22float2(*(__half2*)&raw.y);
        float2 a2 = __half22float2(*(__half2*)&raw.z);
        float2 a3 = __half22float2(*(__half2*)&raw.w);
        float d = q0.x * a0.x + q0.y * a0.y + q0.z * a1.x + q0.w * a1.y
                + q1.x * a2.x + q1.y * a2.y + q1.z * a3.x + q1.w * a3.y;
        s[k] = d * 0.3535533905932738f;   // 1/sqrt(8)
    }

    float m = s[0];
#pragma unroll
    for (int k = 1; k < 16; k++) m = fmaxf(m, s[k]);
    float sum = 0.f;
#pragma unroll
    for (int k = 0; k < 16; k++) { s[k] = __expf(s[k] - m); sum += s[k]; }
    const float inv = 1.0f / sum;

    float o[8];
#pragma unroll
    for (int d = 0; d < 8; d++) o[d] = 0.f;
#pragma unroll
    for (int k = 0; k < 16; k++) {
        uint4 raw = *(const uint4*)(g_v + (size_t)idx[k] * 64 + h * 8);
        float2 a0 = __half22float2(*(__half2*)&raw.x);
        float2 a1 = __half22float2(*(__half2*)&raw.y);
        float2 a2 = __half22float2(*(__half2*)&raw.z);
        float2 a3 = __half22float2(*(__half2*)&raw.w);
        const float p = s[k];
        o[0] += p * a0.x; o[1] += p * a0.y; o[2] += p * a1.x; o[3] += p * a1.y;
        o[4] += p * a2.x; o[5] += p * a2.y; o[6] += p * a3.x; o[7] += p * a3.y;
    }

    {
        const int p_local = tid >> 3;
        float* sp = &sO[p_local * 64 + h * 8];
        *(float4*)(sp)     = make_float4(o[0] * inv, o[1] * inv, o[2] * inv, o[3] * inv);
        *(float4*)(sp + 4) = make_float4(o[4] * inv, o[5] * inv, o[6] * inv, o[7] * inv);
    }
    __syncthreads();

    // ---- Block GEMM: out[32,64] = sO[32,64] @ sWo[64,64] + bo ----
    const int ty = tid >> 5;   // 0..7 : 4-row group
    const int tx = tid & 31;   // col pair

    u64 acc[4];
    {
        const float b0 = bo[2 * tx];
        const float b1 = bo[2 * tx + 1];
#pragma unroll
        for (int r = 0; r < 4; r++) acc[r] = pack2f(b0, b1);
    }

#pragma unroll 8
    for (int i = 0; i < 64; i++) {
        u64 w = *(const u64*)&sWo[i * 64 + 2 * tx];
#pragma unroll
        for (int r = 0; r < 4; r++) {
            float fv = sO[(ty * 4 + r) * 64 + i];
            fma2(acc[r], w, pack2f(fv, fv));
        }
    }

    const int row_base = blockIdx.x * 32 + ty * 4;
#pragma unroll
    for (int r = 0; r < 4; r++) {
        int row = row_base + r;
        if (row < N) {
            float2 v;
            unpack2(acc[r], v.x, v.y);
            *(float2*)&out[(size_t)row * 64 + 2 * tx] = v;
        }
    }
}

// ---------------------------------------------------------------------------
extern "C" void kernel_launch(void* const* d_in, const int* in_sizes, int n_in,
                              void* d_out, int out_size)
{
    const float* feats = (const float*)d_in[0];
    const int*   knn   = (const int*)d_in[1];
    const float* Wq    = (const float*)d_in[2];
    const float* Wk    = (const float*)d_in[3];
    const float* Wv    = (const float*)d_in[4];
    const float* Wo    = (const float*)d_in[5];
    const float* bo    = (const float*)d_in[6];
    float* out = (float*)d_out;

    const int N = in_sizes[0] / CDIM;
    const int ntiles = (N + TILE - 1) / TILE;
    const int attn_blocks = (N * 8 + 255) / 256;
    // smem: 2 fp16 A buffers + W fp16 = 2*9216 + 192*72*2 = 46080 B
    const int qkv_smem_bytes = 2 * ABUF_BYTES + 192 * SK * 2;

    cudaFuncSetAttribute(qkv_kernel, cudaFuncAttributeMaxDynamicSharedMemorySize,
                         qkv_smem_bytes);

    int grid = 296;
    if (grid > ntiles) grid = ntiles;
    qkv_kernel<<<grid, 256, qkv_smem_bytes>>>(feats, Wq, Wk, Wv, N, ntiles);
    attn_kernel<<<attn_blocks, 256>>>(knn, Wo, bo, out, N);
}